// round 2
// baseline (speedup 1.0000x reference)
#include <cuda_runtime.h>

// Problem dims (fixed)
#define BB   512
#define TT   100
#define II   700
#define HH   128
#define OO   20
#define NROWS (BB*TT)
#define NW   22                    // ceil(700/32) mask words per row

#define ALPHA 0.81873075307798182f // exp(-0.2)
#define BETA  0.90483741803595957f // exp(-0.1)
#define LAM   0.95122942450071400f // exp(-0.05)

// Device-global scratch (allocation-free)
static __device__ float    g_W0T[II * HH];                  // W0^T [i][h], 358 KB
static __device__ unsigned g_masks[(size_t)NROWS * NW];     // spike bitmasks, 4.5 MB
static __device__ float    g_U[(size_t)NROWS * HH];         // U = X @ W0^T, 26 MB

// ---------------------------------------------------------------------------
// K1: transpose W0 (H,I) -> W0^T (I,H)
// ---------------------------------------------------------------------------
__global__ void k_transpose_w0(const float* __restrict__ W0) {
    int idx = blockIdx.x * blockDim.x + threadIdx.x;
    if (idx < II * HH) {
        int i = idx >> 7, h = idx & 127;
        g_W0T[idx] = W0[h * II + i];
    }
}

// ---------------------------------------------------------------------------
// K2: spike bitmask extraction. Warp per row; lane w keeps word w.
// DRAM-bound: reads X once (143 MB), writes 4.5 MB of masks.
// ---------------------------------------------------------------------------
__global__ void __launch_bounds__(256) k_masks(const float* __restrict__ X) {
    int warp = (blockIdx.x * 256 + threadIdx.x) >> 5;
    int lane = threadIdx.x & 31;
    if (warp >= NROWS) return;
    const float* xr = X + (size_t)warp * II;
    unsigned mw = 0;
    #pragma unroll
    for (int w = 0; w < NW; w++) {
        int i0 = w * 32 + lane;
        float xv = (i0 < II) ? __ldg(xr + i0) : 0.0f;
        unsigned m = __ballot_sync(0xffffffffu, xv != 0.0f);
        if (lane == w) mw = m;
    }
    if (lane < NW) g_masks[(size_t)warp * NW + lane] = mw;
}

// ---------------------------------------------------------------------------
// K3: sparse gather U[row, half] = sum_{active i} W0T[i, half].
// Each CTA holds a 179 KB half of W0^T in SMEM (gridDim.y = half).
// Warp per row; lane covers 2 h via float2 (64 h per half).
// ---------------------------------------------------------------------------
__global__ void __launch_bounds__(512, 1) k_gather() {
    extern __shared__ float2 Ws2[];            // [700][32] float2 = 179,200 B
    const int half = blockIdx.y;

    for (int idx = threadIdx.x; idx < II * 32; idx += 512) {
        int i = idx >> 5, c = idx & 31;
        Ws2[idx] = *(const float2*)(g_W0T + i * HH + half * 64 + c * 2);
    }
    __syncthreads();

    int warp = threadIdx.x >> 5, lane = threadIdx.x & 31;
    int rows_per_cta = (NROWS + gridDim.x - 1) / gridDim.x;
    int r0 = blockIdx.x * rows_per_cta;
    int r1 = min(r0 + rows_per_cta, NROWS);

    for (int row = r0 + warp; row < r1; row += 16) {
        unsigned mw = (lane < NW) ? g_masks[(size_t)row * NW + lane] : 0u;
        float2 acc = make_float2(0.f, 0.f);
        #pragma unroll 4
        for (int w = 0; w < NW; w++) {
            unsigned m = __shfl_sync(0xffffffffu, mw, w);
            int base = w * 32;
            while (m) {
                int j = __ffs(m) - 1;
                m &= m - 1;
                float2 v = Ws2[(base + j) * 32 + lane];
                acc.x += v.x; acc.y += v.y;
            }
        }
        ((float2*)(g_U + (size_t)row * HH + half * 64))[lane] = acc;
    }
}

// ---------------------------------------------------------------------------
// K4: recurrent phase — warp per sample, NO barriers.
// Lane owns neurons {lane, lane+32, lane+64, lane+96}; spike state is
// exchanged purely via __ballot_sync. W1^T/V1^T stride-129 in SMEM.
// ---------------------------------------------------------------------------
__global__ void __launch_bounds__(128, 1) k_phase2(
    const float* __restrict__ W1, const float* __restrict__ V1,
    const float* __restrict__ Wr, const float* __restrict__ br,
    float* __restrict__ out)
{
    extern __shared__ float sm[];
    float* W1s = sm;                        // 128*129
    float* V1s = W1s + HH * 129;            // 128*129
    float* Wrs = V1s + HH * 129;            // 128*20 (+64 pad at alloc)

    for (int idx = threadIdx.x; idx < HH * HH; idx += 128) {
        int h = idx >> 7, j = idx & 127;
        W1s[j * 129 + h] = W1[idx];
        V1s[j * 129 + h] = V1[idx];
    }
    for (int idx = threadIdx.x; idx < OO * HH; idx += 128) {
        int o = idx >> 7, j = idx & 127;
        Wrs[j * OO + o] = Wr[idx];
    }
    __syncthreads();

    int warp = threadIdx.x >> 5, lane = threadIdx.x & 31;
    int b = blockIdx.x * 4 + warp;
    int ro = (lane < OO) ? lane : 0;        // clamp lane for safe Wr reads

    float s0[4] = {0,0,0,0}, m0v[4] = {0,0,0,0};
    float s1[4] = {0,0,0,0}, m1v[4] = {0,0,0,0};
    unsigned p[4] = {0,0,0,0};
    float rp = 0.f;
    float brv = (lane < OO) ? br[lane] : 0.f;

    const float* Ub  = g_U + (size_t)b * TT * HH;
    float*      outb = out + (size_t)b * TT * OO;

    float u[4], un[4];
    #pragma unroll
    for (int r = 0; r < 4; r++) u[r] = Ub[r * 32 + lane];

    for (int t = 0; t < TT; t++) {
        #pragma unroll
        for (int r = 0; r < 4; r++)
            un[r] = (t + 1 < TT) ? Ub[(t + 1) * HH + r * 32 + lane] : 0.f;

        // Layer 0 LIF
        unsigned k0[4];
        #pragma unroll
        for (int r = 0; r < 4; r++) {
            s0[r] = ALPHA * s0[r] + u[r];
            m0v[r] = BETA * m0v[r] + s0[r];
            bool sp = m0v[r] > 1.0f;
            if (sp) m0v[r] = 0.f;
            k0[r] = __ballot_sync(0xffffffffu, sp);
        }

        // Recurrent gathers: k0 (this step) @ W1^T, k1 (prev step) @ V1^T
        float aW[4] = {0,0,0,0}, aV[4] = {0,0,0,0};
        #pragma unroll
        for (int q = 0; q < 4; q++) {
            unsigned m = k0[q];
            while (m) {
                int j = __ffs(m) - 1; m &= m - 1;
                const float* wr = W1s + (q * 32 + j) * 129;
                #pragma unroll
                for (int r = 0; r < 4; r++) aW[r] += wr[r * 32 + lane];
            }
            m = p[q];
            while (m) {
                int j = __ffs(m) - 1; m &= m - 1;
                const float* vr = V1s + (q * 32 + j) * 129;
                #pragma unroll
                for (int r = 0; r < 4; r++) aV[r] += vr[r * 32 + lane];
            }
        }

        // Layer 1 LIF
        #pragma unroll
        for (int r = 0; r < 4; r++) {
            s1[r] = (ALPHA * s1[r] + aW[r]) + aV[r];
            m1v[r] = BETA * m1v[r] + s1[r];
            bool sp = m1v[r] > 1.0f;
            if (sp) m1v[r] = 0.f;
            p[r] = __ballot_sync(0xffffffffu, sp);
        }

        // Leaky readout (lanes 0..19)
        float racc = brv;
        #pragma unroll
        for (int q = 0; q < 4; q++) {
            unsigned m = p[q];
            while (m) {
                int j = __ffs(m) - 1; m &= m - 1;
                racc += Wrs[(q * 32 + j) * OO + ro];
            }
        }
        rp = LAM * rp + (1.0f - LAM) * racc;
        if (lane < OO) outb[t * OO + lane] = rp;

        #pragma unroll
        for (int r = 0; r < 4; r++) u[r] = un[r];
    }
}

// ---------------------------------------------------------------------------
// Launch
// ---------------------------------------------------------------------------
extern "C" void kernel_launch(void* const* d_in, const int* in_sizes, int n_in,
                              void* d_out, int out_size) {
    (void)in_sizes; (void)n_in; (void)out_size;
    const float* X  = (const float*)d_in[0];
    const float* W0 = (const float*)d_in[1];
    const float* W1 = (const float*)d_in[2];
    const float* V1 = (const float*)d_in[3];
    const float* Wr = (const float*)d_in[4];
    const float* br = (const float*)d_in[5];
    float* out = (float*)d_out;

    k_transpose_w0<<<(II * HH + 255) / 256, 256>>>(W0);
    k_masks<<<(NROWS * 32 + 255) / 256, 256>>>(X);

    const size_t smem_g = (size_t)II * 32 * sizeof(float2);   // 179,200 B
    cudaFuncSetAttribute(k_gather, cudaFuncAttributeMaxDynamicSharedMemorySize,
                         (int)smem_g);
    k_gather<<<dim3(148, 2), 512, smem_g>>>();

    const size_t smem_p2 = (size_t)(2 * HH * 129 + HH * OO + 64) * sizeof(float);
    cudaFuncSetAttribute(k_phase2, cudaFuncAttributeMaxDynamicSharedMemorySize,
                         (int)smem_p2);
    k_phase2<<<BB / 4, 128, smem_p2>>>(W1, V1, Wr, br, out);
}

// round 3
// speedup vs baseline: 1.2848x; 1.2848x over previous
#include <cuda_runtime.h>

// Problem dims (fixed)
#define BB   512
#define TT   100
#define II   700
#define HH   128
#define OO   20
#define NROWS (BB*TT)
#define NW   22                    // ceil(700/32) mask words per row

#define ALPHA 0.81873075307798182f // exp(-0.2)
#define BETA  0.90483741803595957f // exp(-0.1)
#define LAM   0.95122942450071400f // exp(-0.05)

// Device-global scratch (allocation-free)
static __device__ float    g_W0T[II * HH];               // W0^T [i][h]
static __device__ unsigned g_masks[(size_t)NROWS * NW];  // input spike bitmasks
static __device__ float    g_U[(size_t)NROWS * HH];      // U = X @ W0^T
static __device__ unsigned g_K0[(size_t)NROWS * 4];      // layer-0 spike masks
static __device__ float    g_G[(size_t)NROWS * HH];      // G = k0 @ W1^T
static __device__ unsigned g_K1[(size_t)NROWS * 4];      // layer-1 spike masks
static __device__ float    g_Y[(size_t)NROWS * OO];      // y = k1 @ Wr^T + br

// ---------------------------------------------------------------------------
// K1: transpose W0 (H,I) -> W0^T (I,H)
// ---------------------------------------------------------------------------
__global__ void k_transpose_w0(const float* __restrict__ W0) {
    int idx = blockIdx.x * blockDim.x + threadIdx.x;
    if (idx < II * HH) {
        int i = idx >> 7, h = idx & 127;
        g_W0T[idx] = W0[h * II + i];
    }
}

// ---------------------------------------------------------------------------
// K2: input spike bitmask extraction (warp per row). DRAM-bound (143 MB).
// ---------------------------------------------------------------------------
__global__ void __launch_bounds__(256) k_masks(const float* __restrict__ X) {
    int warp = (blockIdx.x * 256 + threadIdx.x) >> 5;
    int lane = threadIdx.x & 31;
    if (warp >= NROWS) return;
    const float* xr = X + (size_t)warp * II;
    unsigned mw = 0;
    #pragma unroll
    for (int w = 0; w < NW; w++) {
        int i0 = w * 32 + lane;
        float xv = (i0 < II) ? __ldg(xr + i0) : 0.0f;
        unsigned m = __ballot_sync(0xffffffffu, xv != 0.0f);
        if (lane == w) mw = m;
    }
    if (lane < NW) g_masks[(size_t)warp * NW + lane] = mw;
}

// ---------------------------------------------------------------------------
// K3: U[row, half] = sum over active i of W0T[i, half]. 179 KB SMEM half/CTA.
// ---------------------------------------------------------------------------
__global__ void __launch_bounds__(512, 1) k_gather() {
    extern __shared__ float2 Ws2[];            // [700][32] float2
    const int half = blockIdx.y;

    for (int idx = threadIdx.x; idx < II * 32; idx += 512) {
        int i = idx >> 5, c = idx & 31;
        Ws2[idx] = *(const float2*)(g_W0T + i * HH + half * 64 + c * 2);
    }
    __syncthreads();

    int warp = threadIdx.x >> 5, lane = threadIdx.x & 31;
    int rows_per_cta = (NROWS + gridDim.x - 1) / gridDim.x;
    int r0 = blockIdx.x * rows_per_cta;
    int r1 = min(r0 + rows_per_cta, NROWS);

    for (int row = r0 + warp; row < r1; row += 16) {
        unsigned mw = (lane < NW) ? g_masks[(size_t)row * NW + lane] : 0u;
        float2 acc = make_float2(0.f, 0.f);
        #pragma unroll 4
        for (int w = 0; w < NW; w++) {
            unsigned m = __shfl_sync(0xffffffffu, mw, w);
            int base = w * 32;
            while (m) {
                int j = __ffs(m) - 1;
                m &= m - 1;
                float2 v = Ws2[(base + j) * 32 + lane];
                acc.x += v.x; acc.y += v.y;
            }
        }
        ((float2*)(g_U + (size_t)row * HH + half * 64))[lane] = acc;
    }
}

// ---------------------------------------------------------------------------
// K4: layer-0 LIF scan (gather-free). Warp = (sample, 32-neuron chunk).
// 2048 independent warps, no barriers. Emits k0 masks.
// ---------------------------------------------------------------------------
__global__ void __launch_bounds__(256) k_layer0() {
    int w = blockIdx.x * 8 + (threadIdx.x >> 5);
    int lane = threadIdx.x & 31;
    int b = w >> 2, c = w & 3;
    if (b >= BB) return;

    const float* Ub = g_U + (size_t)b * TT * HH + c * 32 + lane;
    unsigned* K0b = g_K0 + (size_t)b * TT * 4 + c;

    float s0 = 0.f, m0 = 0.f;
    float u = Ub[0];
    for (int t = 0; t < TT; t++) {
        float un = (t + 1 < TT) ? Ub[(t + 1) * HH] : 0.f;
        s0 = ALPHA * s0 + u;
        m0 = BETA * m0 + s0;
        bool sp = m0 > 1.0f;
        if (sp) m0 = 0.f;
        unsigned bm = __ballot_sync(0xffffffffu, sp);
        if (lane == 0) K0b[(size_t)t * 4] = bm;
        u = un;
    }
}

// ---------------------------------------------------------------------------
// K5: G[row] = sum over active j (k0) of W1T[j]. W1^T in 64 KB SMEM,
// warp per row, float4 per lane.
// ---------------------------------------------------------------------------
__global__ void __launch_bounds__(512) k_gatherG(const float* __restrict__ W1) {
    extern __shared__ float W1s[];             // [128][128], W1s[j*128+h]=W1[h][j]
    for (int idx = threadIdx.x; idx < HH * HH; idx += 512) {
        int h = idx >> 7, j = idx & 127;
        W1s[j * 128 + h] = W1[idx];
    }
    __syncthreads();

    int warp = threadIdx.x >> 5, lane = threadIdx.x & 31;
    int gw = blockIdx.x * 16 + warp;
    int stride = gridDim.x * 16;

    for (int row = gw; row < NROWS; row += stride) {
        unsigned mw = (lane < 4) ? g_K0[(size_t)row * 4 + lane] : 0u;
        float4 acc = make_float4(0.f, 0.f, 0.f, 0.f);
        #pragma unroll
        for (int q = 0; q < 4; q++) {
            unsigned m = __shfl_sync(0xffffffffu, mw, q);
            int base = q * 32;
            while (m) {
                int j = __ffs(m) - 1;
                m &= m - 1;
                float4 v = *(const float4*)(W1s + (base + j) * 128 + lane * 4);
                acc.x += v.x; acc.y += v.y; acc.z += v.z; acc.w += v.w;
            }
        }
        *(float4*)(g_G + (size_t)row * HH + lane * 4) = acc;
    }
}

// ---------------------------------------------------------------------------
// K6: serial layer-1 recurrence ONLY. Thread-per-neuron, 2 samples per CTA
// (256 thr), grid 256 -> ~16 warps/SM. Per-sample named barrier; masks
// double-buffered in SMEM. Emits k1 masks for the readout kernels.
// ---------------------------------------------------------------------------
__global__ void __launch_bounds__(256, 2) k_layer1(const float* __restrict__ V1) {
    extern __shared__ float sm6[];
    float* V1s = sm6;                              // [128][128]
    unsigned* km = (unsigned*)(V1s + HH * HH);     // [2 samples][2 bufs][4]

    for (int idx = threadIdx.x; idx < HH * HH; idx += 256) {
        int h = idx >> 7, j = idx & 127;
        V1s[j * 128 + h] = V1[idx];
    }
    __syncthreads();

    int g = threadIdx.x >> 7;        // sample in CTA
    int h = threadIdx.x & 127;       // neuron
    int word = h >> 5;
    int lane = threadIdx.x & 31;
    int b = blockIdx.x * 2 + g;
    unsigned* kg = km + g * 8;
    int barid = g + 1;

    const float* Gb = g_G + (size_t)b * TT * HH;
    unsigned* K1b = g_K1 + (size_t)b * TT * 4;

    float s1 = 0.f, m1 = 0.f;
    unsigned p0 = 0, p1 = 0, p2 = 0, p3 = 0;   // prev-step k1 masks
    float gv = Gb[h];

    for (int t = 0; t < TT; t++) {
        float gn = (t + 1 < TT) ? Gb[(t + 1) * HH + h] : 0.f;

        float acc = 0.f;
        unsigned m;
        m = p0; while (m) { int j = __ffs(m) - 1; m &= m - 1; acc += V1s[j * 128 + h]; }
        m = p1; while (m) { int j = __ffs(m) - 1; m &= m - 1; acc += V1s[(32 + j) * 128 + h]; }
        m = p2; while (m) { int j = __ffs(m) - 1; m &= m - 1; acc += V1s[(64 + j) * 128 + h]; }
        m = p3; while (m) { int j = __ffs(m) - 1; m &= m - 1; acc += V1s[(96 + j) * 128 + h]; }

        s1 = (ALPHA * s1 + gv) + acc;
        m1 = BETA * m1 + s1;
        bool sp = m1 > 1.0f;
        if (sp) m1 = 0.f;

        unsigned bm = __ballot_sync(0xffffffffu, sp);
        int buf = (t & 1) * 4;
        if (lane == 0) {
            kg[buf + word] = bm;
            K1b[(size_t)t * 4 + word] = bm;
        }
        asm volatile("bar.sync %0, %1;" :: "r"(barid), "r"(128) : "memory");
        p0 = kg[buf + 0]; p1 = kg[buf + 1]; p2 = kg[buf + 2]; p3 = kg[buf + 3];
        gv = gn;
    }
}

// ---------------------------------------------------------------------------
// K7: y[row] = br + sum over active j (k1) of Wr^T[j]. Warp per row.
// ---------------------------------------------------------------------------
__global__ void __launch_bounds__(256) k_readout(const float* __restrict__ Wr,
                                                const float* __restrict__ br) {
    extern __shared__ float sm7[];
    float* Wrs = sm7;              // [128][20]
    float* brs = Wrs + HH * OO;    // [20]
    for (int idx = threadIdx.x; idx < OO * HH; idx += 256) {
        int o = idx >> 7, j = idx & 127;
        Wrs[j * OO + o] = Wr[idx];
    }
    if (threadIdx.x < OO) brs[threadIdx.x] = br[threadIdx.x];
    __syncthreads();

    int warp = threadIdx.x >> 5, lane = threadIdx.x & 31;
    int ro = (lane < OO) ? lane : 0;
    int gw = blockIdx.x * 8 + warp;
    int stride = gridDim.x * 8;

    for (int row = gw; row < NROWS; row += stride) {
        unsigned mw = (lane < 4) ? g_K1[(size_t)row * 4 + lane] : 0u;
        float acc = brs[ro];
        #pragma unroll
        for (int q = 0; q < 4; q++) {
            unsigned m = __shfl_sync(0xffffffffu, mw, q);
            int base = q * 32;
            while (m) {
                int j = __ffs(m) - 1;
                m &= m - 1;
                acc += Wrs[(base + j) * OO + ro];
            }
        }
        if (lane < OO) g_Y[(size_t)row * OO + lane] = acc;
    }
}

// ---------------------------------------------------------------------------
// K8: leaky readout scan. Thread per (b, o); 100-step FMA chain.
// ---------------------------------------------------------------------------
__global__ void k_scan(float* __restrict__ out) {
    int idx = blockIdx.x * blockDim.x + threadIdx.x;
    if (idx >= BB * OO) return;
    int b = idx / OO, o = idx % OO;
    const float* Yb = g_Y + (size_t)b * TT * OO + o;
    float* ob = out + (size_t)b * TT * OO + o;
    const float C = 1.0f - LAM;
    float rp = 0.f;
    #pragma unroll 4
    for (int t = 0; t < TT; t++) {
        rp = LAM * rp + C * Yb[(size_t)t * OO];
        ob[(size_t)t * OO] = rp;
    }
}

// ---------------------------------------------------------------------------
// Launch
// ---------------------------------------------------------------------------
extern "C" void kernel_launch(void* const* d_in, const int* in_sizes, int n_in,
                              void* d_out, int out_size) {
    (void)in_sizes; (void)n_in; (void)out_size;
    const float* X  = (const float*)d_in[0];
    const float* W0 = (const float*)d_in[1];
    const float* W1 = (const float*)d_in[2];
    const float* V1 = (const float*)d_in[3];
    const float* Wr = (const float*)d_in[4];
    const float* br = (const float*)d_in[5];
    float* out = (float*)d_out;

    k_transpose_w0<<<(II * HH + 255) / 256, 256>>>(W0);
    k_masks<<<(NROWS + 7) / 8, 256>>>(X);

    const size_t smem_g = (size_t)II * 32 * sizeof(float2);   // 179,200 B
    cudaFuncSetAttribute(k_gather, cudaFuncAttributeMaxDynamicSharedMemorySize,
                         (int)smem_g);
    k_gather<<<dim3(148, 2), 512, smem_g>>>();

    k_layer0<<<256, 256>>>();

    const size_t smem_g1 = (size_t)HH * HH * sizeof(float);   // 64 KB
    cudaFuncSetAttribute(k_gatherG, cudaFuncAttributeMaxDynamicSharedMemorySize,
                         (int)smem_g1);
    k_gatherG<<<296, 512, smem_g1>>>(W1);

    const size_t smem_l1 = (size_t)HH * HH * sizeof(float) + 16 * sizeof(unsigned);
    cudaFuncSetAttribute(k_layer1, cudaFuncAttributeMaxDynamicSharedMemorySize,
                         (int)smem_l1);
    k_layer1<<<256, 256, smem_l1>>>(V1);

    const size_t smem_ro = (size_t)(HH * OO + OO + 4) * sizeof(float);
    k_readout<<<296, 256, smem_ro>>>(Wr, br);

    k_scan<<<(BB * OO + 255) / 256, 256>>>(out);
}